// round 17
// baseline (speedup 1.0000x reference)
#include <cuda_runtime.h>
#include <cuda_fp16.h>
#include <cstdint>
#include <cstddef>

#define T_STEPS 8192
#define I_DIM   64
#define H_DIM   2048
#define O_DIM   128
#define R4H     8192
#define G_CTA   128
#define UNITS   16              // hidden units per CTA (128*16 = 2048, exact)
#define NTH     544             // 16 dot warps + 1 poller warp
#define NWARP   17
#define POLL_W  16
#define ROW_U4  256             // one weight row: 2048 halfs = 256 uint4
// dyn smem: 32 weight rows (2/unit) * 4KB + 4KB h buffer
#define SMEM_DYN_BYTES (32 * ROW_U4 * 16 + ROW_U4 * 16)

// ---------------- device-global scratch (no runtime allocation) -------------
__device__ __half g_w16[(size_t)R4H * H_DIM];    // 32 MB fp16 W_hh, unit-major rows
__device__ float  g_xg[(size_t)T_STEPS * R4H];   // 256 MB x_gates [t][4*unit+gate]
// per-CTA publish slots: 128B line each; [0],[1] = 16 halfs of h, [2].x = tag
__device__ __align__(128) uint4 g_slot[2][G_CTA][8];

__device__ __forceinline__ float tanh_fast(float x) {
    float r;
    asm("tanh.approx.f32 %0, %1;" : "=f"(r) : "f"(x));
    return r;
}
__device__ __forceinline__ float sig_fast(float x) {
    return fmaf(tanh_fast(0.5f * x), 0.5f, 0.5f);
}

// ---------------- init: zero slots + tags (h(0) = 0, tags = 0) --------------
__global__ void init_k() {
    uint4 z = make_uint4(0u, 0u, 0u, 0u);
    uint4* p = &g_slot[0][0][0];
    for (int i = threadIdx.x; i < 2 * G_CTA * 8; i += blockDim.x) p[i] = z;
}

// ---------------- W_hh fp32 -> fp16, rows permuted unit-major ----------------
// orig row r = gate*2048 + unit -> prow = 4*unit + gate
__global__ __launch_bounds__(256) void prep_w(const float* __restrict__ Whh) {
    int r = blockIdx.x;
    int prow = 4 * (r & (H_DIM - 1)) + (r >> 11);
    __half* dst = g_w16 + (size_t)prow * H_DIM;
    const float* src = Whh + (size_t)r * H_DIM;
    for (int k = threadIdx.x; k < H_DIM; k += 256)
        dst[k] = __float2half_rn(src[k]);
}

// ---------------- x_gates GEMM: g_xg[t][prow] = input[t]·W_ih[row] + biases --
__global__ __launch_bounds__(256) void xg_kernel(const float* __restrict__ inp,
                                                 const float* __restrict__ Wih,
                                                 const float* __restrict__ bih,
                                                 const float* __restrict__ bhh) {
    __shared__ float sI[64][64];
    __shared__ float sW[64][65];
    int t0b = blockIdx.x * 64;
    int r0b = blockIdx.y * 64;
    int tid = threadIdx.x;

    for (int i = tid; i < 64 * 16; i += 256) {
        int row = i >> 4, q = i & 15;
        float4 v = *(const float4*)(inp + (size_t)(t0b + row) * I_DIM + q * 4);
        *(float4*)(&sI[row][q * 4]) = v;
        float4 w = *(const float4*)(Wih + (size_t)(r0b + row) * I_DIM + q * 4);
        sW[row][q * 4 + 0] = w.x; sW[row][q * 4 + 1] = w.y;
        sW[row][q * 4 + 2] = w.z; sW[row][q * 4 + 3] = w.w;
    }
    __syncthreads();

    int tx = tid & 15, ty = tid >> 4;
    int rr = tx * 4, tt = ty * 4;
    float acc[4][4] = {};
#pragma unroll
    for (int k = 0; k < 64; k++) {
        float w0 = sW[rr + 0][k], w1 = sW[rr + 1][k];
        float w2 = sW[rr + 2][k], w3 = sW[rr + 3][k];
#pragma unroll
        for (int i = 0; i < 4; i++) {
            float x = sI[tt + i][k];
            acc[i][0] = fmaf(x, w0, acc[i][0]);
            acc[i][1] = fmaf(x, w1, acc[i][1]);
            acc[i][2] = fmaf(x, w2, acc[i][2]);
            acc[i][3] = fmaf(x, w3, acc[i][3]);
        }
    }
#pragma unroll
    for (int j = 0; j < 4; j++) {
        int r = r0b + rr + j;
        int prow = 4 * (r & (H_DIM - 1)) + (r >> 11);
        float b = bih[r] + bhh[r];
#pragma unroll
        for (int i = 0; i < 4; i++)
            g_xg[(size_t)(t0b + tt + i) * R4H + prow] = acc[i][j] + b;
    }
}

// ---------------- persistent recurrence kernel -------------------------------
__global__ void __launch_bounds__(NTH, 1) lstm_main(const float* __restrict__ Wlin,
                                                    const float* __restrict__ blin,
                                                    float* __restrict__ out) {
    extern __shared__ __align__(16) unsigned char smem_raw[];
    uint4* s_w = (uint4*)smem_raw;          // 32 rows x 256 uint4 (rows 0,1 per unit)
    uint4* s_h = s_w + 32 * ROW_U4;         // 256 uint4 = full h, compact
    __shared__ __align__(16) __half s_hout[16];
    __shared__ unsigned s_flag;             // poller: fan of h(t) done => flag = t+1
    __shared__ float    swr[NWARP];

    int cta  = blockIdx.x;
    int tid  = threadIdx.x;
    int wid  = tid >> 5;
    int lane = tid & 31;
    int ugl  = cta * UNITS + wid;           // owned hidden unit (dot warps)

    if (tid == 0) s_flag = 0u;

    // stage weights: rows 0,1 of owned unit -> SMEM; rows 2,3 -> registers
    uint4 wreg[16];
    if (wid < UNITS) {
        const uint4* wsrc = ((const uint4*)g_w16) + (size_t)(4 * ugl) * ROW_U4;
#pragma unroll
        for (int j = 0; j < 2; j++) {
            uint4* dst = s_w + (size_t)(2 * wid + j) * ROW_U4;
#pragma unroll
            for (int k = 0; k < 8; k++)
                dst[k * 32 + lane] = __ldg(wsrc + (size_t)j * ROW_U4 + k * 32 + lane);
        }
#pragma unroll
        for (int j = 0; j < 2; j++)
#pragma unroll
            for (int k = 0; k < 8; k++)
                wreg[j * 8 + k] = __ldg(wsrc + (size_t)(2 + j) * ROW_U4 + k * 32 + lane);
    }
    __syncthreads();

    if (wid == POLL_W) {
        // ---- poller warp: decentralized tag barrier + h fan-in -------------
        // lane owns tags of slots 4*lane .. 4*lane+3 (relaxed poll + ballot)
        for (int t = 0; t <= T_STEPS; t++) {
            int b = t & 1;
            const unsigned* tg0 = &g_slot[b][4 * lane + 0][2].x;
            const unsigned* tg1 = &g_slot[b][4 * lane + 1][2].x;
            const unsigned* tg2 = &g_slot[b][4 * lane + 2][2].x;
            const unsigned* tg3 = &g_slot[b][4 * lane + 3][2].x;
            unsigned bal;
            do {
                unsigned v0, v1, v2, v3;
                asm volatile("ld.relaxed.gpu.global.u32 %0, [%1];" : "=r"(v0) : "l"(tg0));
                asm volatile("ld.relaxed.gpu.global.u32 %0, [%1];" : "=r"(v1) : "l"(tg1));
                asm volatile("ld.relaxed.gpu.global.u32 %0, [%1];" : "=r"(v2) : "l"(tg2));
                asm volatile("ld.relaxed.gpu.global.u32 %0, [%1];" : "=r"(v3) : "l"(tg3));
                bool ok = (v0 >= (unsigned)t) & (v1 >= (unsigned)t) &
                          (v2 >= (unsigned)t) & (v3 >= (unsigned)t);
                bal = __ballot_sync(0xffffffffu, ok);
            } while (bal != 0xffffffffu);
            asm volatile("fence.acq_rel.gpu;" ::: "memory");
            // transposed fan: element i = lane + 32j -> slot i>>1, half i&1
            // (coalesced LDG, conflict-free STS)
#pragma unroll
            for (int j = 0; j < 8; j++) {
                int i = lane + 32 * j;
                uint4 d = __ldcg(&g_slot[b][i >> 1][i & 1]);
                s_h[i] = d;
            }
            asm volatile("bar.sync 1, 32;" ::: "memory");   // drain STS
            if (lane == 0)
                asm volatile("st.release.cta.shared.u32 [%0], %1;"
                             :: "l"((size_t)__cvta_generic_to_shared(&s_flag)),
                                "r"((unsigned)(t + 1)) : "memory");
        }
    } else {
        // ---- dot warp: owns unit ugl; rows 0,1 in SMEM, rows 2,3 in regs ---
        const uint4* wrow = s_w + (size_t)(2 * wid) * ROW_U4;
        float c_val = 0.0f;

        for (int t = 0; t < T_STEPS; t++) {
            // xg prefetch (immutable; overlaps the spin)
            float4 xgv = make_float4(0.f, 0.f, 0.f, 0.f);
            if (lane == 0)
                xgv = *(const float4*)(g_xg + (size_t)t * R4H + 4 * ugl);

            // wait for h(t) fan (SMEM spin)
            unsigned f;
            do {
                asm volatile("ld.acquire.cta.shared.u32 %0, [%1];"
                             : "=r"(f)
                             : "l"((size_t)__cvta_generic_to_shared(&s_flag))
                             : "memory");
            } while (f < (unsigned)(t + 1));

            __half2 acc[4][2];
#pragma unroll
            for (int j = 0; j < 4; j++) {
                acc[j][0] = __float2half2_rn(0.0f);
                acc[j][1] = __float2half2_rn(0.0f);
            }
#pragma unroll
            for (int kh = 0; kh < 2; kh++) {
                uint4 hv[4];
#pragma unroll
                for (int k = 0; k < 4; k++)
                    hv[k] = s_h[(kh * 4 + k) * 32 + lane];
                // SMEM rows (gates i, f)
#pragma unroll
                for (int j = 0; j < 2; j++) {
#pragma unroll
                    for (int k = 0; k < 4; k++) {
                        uint4 w = wrow[(size_t)j * ROW_U4 + (kh * 4 + k) * 32 + lane];
                        acc[j][0] = __hfma2(*(const __half2*)&w.x, *(const __half2*)&hv[k].x, acc[j][0]);
                        acc[j][1] = __hfma2(*(const __half2*)&w.y, *(const __half2*)&hv[k].y, acc[j][1]);
                        acc[j][0] = __hfma2(*(const __half2*)&w.z, *(const __half2*)&hv[k].z, acc[j][0]);
                        acc[j][1] = __hfma2(*(const __half2*)&w.w, *(const __half2*)&hv[k].w, acc[j][1]);
                    }
                }
                // register rows (gates g, o)
#pragma unroll
                for (int j = 0; j < 2; j++) {
#pragma unroll
                    for (int k = 0; k < 4; k++) {
                        uint4 w = wreg[j * 8 + kh * 4 + k];
                        acc[2 + j][0] = __hfma2(*(const __half2*)&w.x, *(const __half2*)&hv[k].x, acc[2 + j][0]);
                        acc[2 + j][1] = __hfma2(*(const __half2*)&w.y, *(const __half2*)&hv[k].y, acc[2 + j][1]);
                        acc[2 + j][0] = __hfma2(*(const __half2*)&w.z, *(const __half2*)&hv[k].z, acc[2 + j][0]);
                        acc[2 + j][1] = __hfma2(*(const __half2*)&w.w, *(const __half2*)&hv[k].w, acc[2 + j][1]);
                    }
                }
            }
            float s[4];
#pragma unroll
            for (int j = 0; j < 4; j++) {
                float2 f0 = __half22float2(acc[j][0]);
                float2 f1 = __half22float2(acc[j][1]);
                s[j] = (f0.x + f0.y) + (f1.x + f1.y);
            }
#pragma unroll
            for (int sh = 16; sh > 0; sh >>= 1) {
                s[0] += __shfl_xor_sync(0xffffffffu, s[0], sh);
                s[1] += __shfl_xor_sync(0xffffffffu, s[1], sh);
                s[2] += __shfl_xor_sync(0xffffffffu, s[2], sh);
                s[3] += __shfl_xor_sync(0xffffffffu, s[3], sh);
            }

            if (lane == 0) {
                float xi = s[0] + xgv.x;
                float xf = s[1] + xgv.y;
                float xg = s[2] + xgv.z;
                float xo = s[3] + xgv.w;
                float ig = sig_fast(xi);
                float fg = sig_fast(xf);
                float gg = tanh_fast(xg);
                float og = sig_fast(xo);
                c_val = fg * c_val + ig * gg;
                float h = og * tanh_fast(c_val);
                s_hout[wid] = __float2half_rn(h);
            }
            __syncwarp();

            if (wid == 0) {
                // collect all 16 units (BAR drains owners' STS), publish slot
                asm volatile("bar.sync 2, %0;" :: "r"(UNITS * 32) : "memory");
                if (lane == 0) {
                    uint4 p0 = *(const uint4*)(s_hout);
                    uint4 p1 = *(const uint4*)(s_hout + 8);
                    uint4* slot = &g_slot[(t + 1) & 1][cta][0];
                    __stcg(slot, p0);
                    __stcg(slot + 1, p1);
                    asm volatile("st.release.gpu.global.u32 [%0], %1;"
                                 :: "l"(&slot[2].x), "r"((unsigned)(t + 1)) : "memory");
                }
            } else {
                asm volatile("bar.arrive 2, %0;" :: "r"(UNITS * 32) : "memory");
            }
        }
    }

    __syncthreads();   // poller's t=T fan done => s_h holds h(T), all tags >= T

    // ---- final linear: CTA o computes out[o] = h_T · W_lin[o] + b_lin[o] ----
    {
        const float* wrow = Wlin + (size_t)cta * H_DIM;
        const __half* hh = (const __half*)s_h;
        float s = 0.0f;
        for (int k = tid; k < H_DIM; k += NTH)
            s = fmaf(__half2float(hh[k]), __ldg(wrow + k), s);
#pragma unroll
        for (int sh = 16; sh > 0; sh >>= 1)
            s += __shfl_xor_sync(0xffffffffu, s, sh);
        if (lane == 0) swr[wid] = s;
        __syncthreads();
        if (tid == 0) {
            float tot = 0.0f;
#pragma unroll
            for (int w = 0; w < NWARP; w++) tot += swr[w];
            out[cta] = tot + __ldg(blin + cta);
        }
    }
}

// ---------------- launch ------------------------------------------------------
extern "C" void kernel_launch(void* const* d_in, const int* in_sizes, int n_in,
                              void* d_out, int out_size) {
    const float* inp  = (const float*)d_in[0];
    const float* Wih  = (const float*)d_in[1];
    const float* Whh  = (const float*)d_in[2];
    const float* bih  = (const float*)d_in[3];
    const float* bhh  = (const float*)d_in[4];
    const float* Wlin = (const float*)d_in[5];
    const float* blin = (const float*)d_in[6];
    float* out = (float*)d_out;
    (void)in_sizes; (void)n_in; (void)out_size;

    cudaFuncSetAttribute(lstm_main, cudaFuncAttributeMaxDynamicSharedMemorySize,
                         SMEM_DYN_BYTES);

    init_k<<<1, 256>>>();
    prep_w<<<R4H, 256>>>(Whh);
    dim3 gx(T_STEPS / 64, R4H / 64);
    xg_kernel<<<gx, 256>>>(inp, Wih, bih, bhh);
    lstm_main<<<G_CTA, NTH, SMEM_DYN_BYTES>>>(Wlin, blin, out);
}